// round 11
// baseline (speedup 1.0000x reference)
#include <cuda_runtime.h>
#include <cuda_bf16.h>
#include <math_constants.h>

#define Nn 50000
#define NF 256
#define NH 64
#define NC 40
#define NE 800000

typedef unsigned long long ull;

// packed f32x2 helpers (FFMA2 path — ptxas won't emit from plain C++)
#define FMA2(acc, a, b) asm("fma.rn.f32x2 %0, %1, %2, %0;" : "+l"(acc) : "l"(a), "l"(b))
#define PACK2(d, lo, hi) asm("mov.b64 %0, {%1, %2};" : "=l"(d) : "f"(lo), "f"(hi))
#define UNPACK2(lo, hi, s) asm("mov.b64 {%0, %1}, %2;" : "=f"(lo), "=f"(hi) : "l"(s))

// -------- device scratch (no allocs allowed) --------
__device__ float g_xw[(size_t)Nn * NH];    // x @ W1
__device__ float g_h[(size_t)Nn * NH];     // relu(A·xw + b1)
__device__ float g_t[(size_t)Nn * NH];     // A·g_h
__device__ int   g_cnt[Nn];                // per-dst edge counts
__device__ int   g_start[Nn];              // per-dst segment start (unsorted layout)
__device__ int   g_cursor[Nn];             // scatter cursors
__device__ int   g_total;                  // global segment allocator
__device__ int2  g_pedge[NE];              // permuted (src, val-bits) grouped by dst

// ---------------- zero counts + allocator ----------------
__global__ __launch_bounds__(256) void zero_cnt() {
    int i = blockIdx.x * 256 + threadIdx.x;
    if (i < Nn) g_cnt[i] = 0;
    if (i == 0) g_total = 0;
}

// ---------------- histogram of dst ----------------
__global__ __launch_bounds__(256) void hist(const int* __restrict__ dst) {
    int e = blockIdx.x * 256 + threadIdx.x;
    if (e < NE) atomicAdd(&g_cnt[dst[e]], 1);
}

// ------- segment assign: disjoint per-row ranges via warp scan + 1 atomic -------
__global__ __launch_bounds__(256) void assign_seg() {
    int i = blockIdx.x * 256 + threadIdx.x;
    int lane = threadIdx.x & 31;
    int c = (i < Nn) ? g_cnt[i] : 0;
    int s = c;
#pragma unroll
    for (int o = 1; o < 32; o <<= 1) {
        int n = __shfl_up_sync(0xFFFFFFFFu, s, o);
        if (lane >= o) s += n;
    }
    int base = 0;
    if (lane == 31) base = atomicAdd(&g_total, s);
    base = __shfl_sync(0xFFFFFFFFu, base, 31);
    int start = base + s - c;
    if (i < Nn) {
        g_start[i] = start;
        g_cursor[i] = start;
    }
}

// ---------------- scatter edges into grouped order ----------------
__global__ __launch_bounds__(256) void scatter(const int* __restrict__ src,
                                               const int* __restrict__ dst,
                                               const float* __restrict__ val) {
    int e = blockIdx.x * 256 + threadIdx.x;
    if (e >= NE) return;
    int d = dst[e];
    int p = atomicAdd(&g_cursor[d], 1);
    g_pedge[p] = make_int2(src[e], __float_as_int(val[e]));
}

// ---- GEMM1: xw = x @ W1 (50000x256 @ 256x64) ----
// BM=256, 256 threads, 8 rows x 8 cols per thread; FFMA2 over M.
// Per k-step per warp: 2 LDS.128 (w) + 4 LDS.64 (a) for 64 MACs/thread ->
// crossbar and fma pipe balanced near the fma floor.
#define G1_STR 258
__global__ __launch_bounds__(256) void gemm1(const float* __restrict__ x,
                                             const float* __restrict__ W1) {
    __shared__ __align__(16) float xs_t[32][G1_STR];  // [k][row], 33KB
    __shared__ __align__(16) float ws[32][64];        // 8KB
    int tid = threadIdx.x;
    int m0 = blockIdx.x * 256;
    int tx = tid & 7;         // col group: c0 = tx*8
    int ty = tid >> 3;        // row group: r0 = ty*8 (32 groups x 8 rows = 256)
    int c0 = tx * 8;
    int r0 = ty * 8;

    ull acc2[4][8];           // [row-pair][col]
#pragma unroll
    for (int j = 0; j < 4; j++)
#pragma unroll
        for (int c = 0; c < 8; c++) acc2[j][c] = 0ull;

    for (int k0 = 0; k0 < NF; k0 += 32) {
        // load x tile 256x32 -> transposed (8 float4 per thread)
#pragma unroll
        for (int p = 0; p < 8; p++) {
            int idx = tid + p * 256;       // 0..2047 float4 slots
            int r   = idx >> 3;
            int kj  = (idx & 7) << 2;
            int row = m0 + r;
            float4 v = make_float4(0.f, 0.f, 0.f, 0.f);
            if (row < Nn)
                v = *reinterpret_cast<const float4*>(&x[(size_t)row * NF + k0 + kj]);
            xs_t[kj + 0][r] = v.x;
            xs_t[kj + 1][r] = v.y;
            xs_t[kj + 2][r] = v.z;
            xs_t[kj + 3][r] = v.w;
        }
        // load W tile 32x64 (2 float4 per thread)
#pragma unroll
        for (int p = 0; p < 2; p++) {
            int idx = tid + p * 256;       // 0..511
            int kk  = idx >> 4;
            int cc  = (idx & 15) << 2;
            float4 v = *reinterpret_cast<const float4*>(&W1[(size_t)(k0 + kk) * NH + cc]);
            *reinterpret_cast<float4*>(&ws[kk][cc]) = v;
        }
        __syncthreads();
#pragma unroll
        for (int k = 0; k < 32; k++) {
            float4 wq0 = *reinterpret_cast<const float4*>(&ws[k][c0]);
            float4 wq1 = *reinterpret_cast<const float4*>(&ws[k][c0 + 4]);
            ull w[8];
            PACK2(w[0], wq0.x, wq0.x); PACK2(w[1], wq0.y, wq0.y);
            PACK2(w[2], wq0.z, wq0.z); PACK2(w[3], wq0.w, wq0.w);
            PACK2(w[4], wq1.x, wq1.x); PACK2(w[5], wq1.y, wq1.y);
            PACK2(w[6], wq1.z, wq1.z); PACK2(w[7], wq1.w, wq1.w);
            const float* xr = &xs_t[k][r0];
            ull a0 = *reinterpret_cast<const ull*>(xr + 0);
            ull a1 = *reinterpret_cast<const ull*>(xr + 2);
            ull a2 = *reinterpret_cast<const ull*>(xr + 4);
            ull a3 = *reinterpret_cast<const ull*>(xr + 6);
#pragma unroll
            for (int c = 0; c < 8; c++) {
                FMA2(acc2[0][c], a0, w[c]);
                FMA2(acc2[1][c], a1, w[c]);
                FMA2(acc2[2][c], a2, w[c]);
                FMA2(acc2[3][c], a3, w[c]);
            }
        }
        __syncthreads();
    }
    // write out: 8 rows x 8 cols per thread
#pragma unroll
    for (int j = 0; j < 4; j++) {
        float e0[8], e1[8];
#pragma unroll
        for (int c = 0; c < 8; c++) UNPACK2(e0[c], e1[c], acc2[j][c]);
        int row = m0 + r0 + 2 * j;
        if (row < Nn) {
            *reinterpret_cast<float4*>(&g_xw[(size_t)row * NH + c0]) =
                make_float4(e0[0], e0[1], e0[2], e0[3]);
            *reinterpret_cast<float4*>(&g_xw[(size_t)row * NH + c0 + 4]) =
                make_float4(e0[4], e0[5], e0[6], e0[7]);
        }
        if (row + 1 < Nn) {
            *reinterpret_cast<float4*>(&g_xw[(size_t)(row + 1) * NH + c0]) =
                make_float4(e1[0], e1[1], e1[2], e1[3]);
            *reinterpret_cast<float4*>(&g_xw[(size_t)(row + 1) * NH + c0 + 4]) =
                make_float4(e1[4], e1[5], e1[6], e1[7]);
        }
    }
}

// ---- SpMM1 gather + bias + relu: g_h[r] = relu(sum_e val*xw[src] + b1) ----
__global__ __launch_bounds__(256) void spmm1g(const float* __restrict__ b1) {
    int r = blockIdx.x * 8 + (threadIdx.x >> 5);
    if (r >= Nn) return;
    int lane = threadIdx.x & 31;
    float2 b = reinterpret_cast<const float2*>(b1)[lane];
    int e0 = g_start[r], e1 = e0 + g_cnt[r];
    float ax = 0.f, ay = 0.f, bx = 0.f, by = 0.f;
    int e = e0;
    for (; e + 2 <= e1; e += 2) {
        int2 ea = g_pedge[e];
        int2 eb = g_pedge[e + 1];
        float2 ta = reinterpret_cast<const float2*>(&g_xw[(size_t)ea.x * NH])[lane];
        float2 tb = reinterpret_cast<const float2*>(&g_xw[(size_t)eb.x * NH])[lane];
        float va = __int_as_float(ea.y);
        float vb = __int_as_float(eb.y);
        ax += va * ta.x; ay += va * ta.y;
        bx += vb * tb.x; by += vb * tb.y;
    }
    if (e < e1) {
        int2 ea = g_pedge[e];
        float2 ta = reinterpret_cast<const float2*>(&g_xw[(size_t)ea.x * NH])[lane];
        float va = __int_as_float(ea.y);
        ax += va * ta.x; ay += va * ta.y;
    }
    reinterpret_cast<float2*>(&g_h[(size_t)r * NH])[lane] =
        make_float2(fmaxf(ax + bx + b.x, 0.f), fmaxf(ay + by + b.y, 0.f));
}

// ---- SpMM2 gather: g_t[r] = sum_e val*g_h[src]  (64 feats) ----
__global__ __launch_bounds__(256) void spmm2k() {
    int r = blockIdx.x * 8 + (threadIdx.x >> 5);
    if (r >= Nn) return;
    int lane = threadIdx.x & 31;
    int e0 = g_start[r], e1 = e0 + g_cnt[r];
    float ax = 0.f, ay = 0.f, bx = 0.f, by = 0.f;
    int e = e0;
    for (; e + 2 <= e1; e += 2) {
        int2 ea = g_pedge[e];
        int2 eb = g_pedge[e + 1];
        float2 ta = reinterpret_cast<const float2*>(&g_h[(size_t)ea.x * NH])[lane];
        float2 tb = reinterpret_cast<const float2*>(&g_h[(size_t)eb.x * NH])[lane];
        float va = __int_as_float(ea.y);
        float vb = __int_as_float(eb.y);
        ax += va * ta.x; ay += va * ta.y;
        bx += vb * tb.x; by += vb * tb.y;
    }
    if (e < e1) {
        int2 ea = g_pedge[e];
        float2 ta = reinterpret_cast<const float2*>(&g_h[(size_t)ea.x * NH])[lane];
        float va = __int_as_float(ea.y);
        ax += va * ta.x; ay += va * ta.y;
    }
    reinterpret_cast<float2*>(&g_t[(size_t)r * NH])[lane] =
        make_float2(ax + bx, ay + by);
}

// ---- GEMM2 + finalize (unchanged from R10) ----
#define G2_STR 68
__global__ __launch_bounds__(320) void gemm2fin(const float* __restrict__ eps,
                                                const float* __restrict__ W11,
                                                const float* __restrict__ b11,
                                                const float* __restrict__ W12,
                                                const float* __restrict__ b12,
                                                float* __restrict__ out) {
    __shared__ __align__(16) float hs_t[64][G2_STR];
    __shared__ __align__(16) float ws2[64][84];
    __shared__ float zs[64][80];
    __shared__ float bs[80];
    int tid = threadIdx.x;
    int r0b = blockIdx.x * 64;

    if (tid < 80) bs[tid] = (tid < NC) ? b11[tid] : b12[tid - NC];
    for (int idx = tid; idx < 64 * 80; idx += 320) {
        int k = idx / 80;
        int j = idx % 80;
        ws2[k][j] = (j < NC) ? W11[(size_t)k * NC + j] : W12[(size_t)k * NC + (j - NC)];
    }
    for (int idx = tid; idx < 1024; idx += 320) {
        int r  = idx >> 4;
        int kj = (idx & 15) << 2;
        int row = r0b + r;
        float4 v = make_float4(0.f, 0.f, 0.f, 0.f);
        if (row < Nn)
            v = *reinterpret_cast<const float4*>(&g_t[(size_t)row * NH + kj]);
        hs_t[kj + 0][r] = v.x;
        hs_t[kj + 1][r] = v.y;
        hs_t[kj + 2][r] = v.z;
        hs_t[kj + 3][r] = v.w;
    }
    __syncthreads();

    int tx = tid % 20;
    int ty = tid / 20;
    int c0 = tx * 4;
    int r0 = ty * 4;

    ull acc2[2][4];
#pragma unroll
    for (int j = 0; j < 2; j++)
#pragma unroll
        for (int c = 0; c < 4; c++) acc2[j][c] = 0ull;

#pragma unroll
    for (int k = 0; k < 64; k++) {
        float4 wq = *reinterpret_cast<const float4*>(&ws2[k][c0]);
        ull w0, w1, w2, w3;
        PACK2(w0, wq.x, wq.x);
        PACK2(w1, wq.y, wq.y);
        PACK2(w2, wq.z, wq.z);
        PACK2(w3, wq.w, wq.w);
        const float* hr = &hs_t[k][r0];
        ull a0 = *reinterpret_cast<const ull*>(hr + 0);
        ull a1 = *reinterpret_cast<const ull*>(hr + 2);
        FMA2(acc2[0][0], a0, w0); FMA2(acc2[0][1], a0, w1);
        FMA2(acc2[0][2], a0, w2); FMA2(acc2[0][3], a0, w3);
        FMA2(acc2[1][0], a1, w0); FMA2(acc2[1][1], a1, w1);
        FMA2(acc2[1][2], a1, w2); FMA2(acc2[1][3], a1, w3);
    }
#pragma unroll
    for (int j = 0; j < 2; j++) {
#pragma unroll
        for (int c = 0; c < 4; c++) {
            float lo, hi;
            UNPACK2(lo, hi, acc2[j][c]);
            zs[r0 + 2 * j][c0 + c]     = lo;
            zs[r0 + 2 * j + 1][c0 + c] = hi;
        }
    }
    __syncthreads();

    int w = tid >> 5;
    int lane = tid & 31;
    for (int r = w; r < 64; r += 10) {
        int row = r0b + r;
        if (row >= Nn) continue;
        const float* zr = zs[r];
        float z0 = eps[(size_t)row * NC + lane] * expf(zr[NC + lane] + bs[NC + lane])
                 + zr[lane] + bs[lane];
        float z1 = -CUDART_INF_F;
        if (lane < 8) {
            int jj = 32 + lane;
            z1 = eps[(size_t)row * NC + jj] * expf(zr[NC + jj] + bs[NC + jj])
               + zr[jj] + bs[jj];
        }
        float mx = fmaxf(z0, z1);
#pragma unroll
        for (int o = 16; o > 0; o >>= 1)
            mx = fmaxf(mx, __shfl_xor_sync(0xFFFFFFFFu, mx, o));
        float sm = expf(z0 - mx) + ((lane < 8) ? expf(z1 - mx) : 0.f);
#pragma unroll
        for (int o = 16; o > 0; o >>= 1)
            sm += __shfl_xor_sync(0xFFFFFFFFu, sm, o);
        float lse = logf(sm) + mx;
        out[(size_t)row * NC + lane] = z0 - lse;
        if (lane < 8)
            out[(size_t)row * NC + 32 + lane] = z1 - lse;
    }
}

extern "C" void kernel_launch(void* const* d_in, const int* in_sizes, int n_in,
                              void* d_out, int out_size) {
    const float* x    = (const float*)d_in[0];
    const int*   esrc = (const int*)d_in[1];
    const int*   edst = (const int*)d_in[2];
    const float* evl  = (const float*)d_in[3];
    const float* eps  = (const float*)d_in[4];
    const float* W1   = (const float*)d_in[5];
    const float* b1   = (const float*)d_in[6];
    const float* W11  = (const float*)d_in[7];
    const float* b11  = (const float*)d_in[8];
    const float* W12  = (const float*)d_in[9];
    const float* b12  = (const float*)d_in[10];
    float* out = (float*)d_out;

    // side stream + events, created once (first call is the non-captured
    // correctness run, so creation never happens during graph capture)
    static cudaStream_t s2 = nullptr;
    static cudaEvent_t evA = nullptr, evB = nullptr;
    if (s2 == nullptr) {
        cudaStreamCreateWithFlags(&s2, cudaStreamNonBlocking);
        cudaEventCreateWithFlags(&evA, cudaEventDisableTiming);
        cudaEventCreateWithFlags(&evB, cudaEventDisableTiming);
    }

    // fork: gemm1 (independent of CSR build) runs on s2
    cudaEventRecord(evA, 0);
    cudaStreamWaitEvent(s2, evA, 0);

    zero_cnt<<<(Nn + 255) / 256, 256>>>();
    hist<<<(NE + 255) / 256, 256>>>(edst);
    assign_seg<<<(Nn + 255) / 256, 256>>>();
    gemm1<<<(Nn + 255) / 256, 256, 0, s2>>>(x, W1);   // 4th submission -> ncu snapshot
    scatter<<<(NE + 255) / 256, 256>>>(esrc, edst, evl);

    // join: spmm1g needs both scatter (stream 0) and gemm1 (s2)
    cudaEventRecord(evB, s2);
    cudaStreamWaitEvent(0, evB, 0);

    spmm1g<<<(Nn + 7) / 8, 256>>>(b1);
    spmm2k<<<(Nn + 7) / 8, 256>>>();
    gemm2fin<<<(Nn + 63) / 64, 320>>>(eps, W11, b11, W12, b12, out);
}

// round 13
// speedup vs baseline: 1.1518x; 1.1518x over previous
#include <cuda_runtime.h>
#include <cuda_bf16.h>
#include <math_constants.h>

#define Nn 50000
#define NF 256
#define NH 64
#define NC 40
#define NE 800000

typedef unsigned long long ull;

// packed f32x2 helpers (FFMA2 path — ptxas won't emit from plain C++)
#define FMA2(acc, a, b) asm("fma.rn.f32x2 %0, %1, %2, %0;" : "+l"(acc) : "l"(a), "l"(b))
#define PACK2(d, lo, hi) asm("mov.b64 %0, {%1, %2};" : "=l"(d) : "f"(lo), "f"(hi))
#define UNPACK2(lo, hi, s) asm("mov.b64 {%0, %1}, %2;" : "=f"(lo), "=f"(hi) : "l"(s))

// -------- device scratch (no allocs allowed) --------
__device__ float g_xw[(size_t)Nn * NH];    // x @ W1
__device__ float g_h[(size_t)Nn * NH];     // relu(A·xw + b1)
__device__ float g_t[(size_t)Nn * NH];     // A·g_h
__device__ int   g_cnt[Nn];                // per-dst edge counts
__device__ int   g_start[Nn];              // per-dst segment start (unsorted layout)
__device__ int   g_cursor[Nn];             // scatter cursors
__device__ int   g_total;                  // global segment allocator
__device__ int2  g_pedge[NE];              // permuted (src, val-bits) grouped by dst

// ---------------- zero counts + allocator ----------------
__global__ __launch_bounds__(256) void zero_cnt() {
    int i = blockIdx.x * 256 + threadIdx.x;
    if (i < Nn) g_cnt[i] = 0;
    if (i == 0) g_total = 0;
}

// ---------------- histogram of dst ----------------
__global__ __launch_bounds__(256) void hist(const int* __restrict__ dst) {
    int e = blockIdx.x * 256 + threadIdx.x;
    if (e < NE) atomicAdd(&g_cnt[dst[e]], 1);
}

// ------- segment assign: disjoint per-row ranges via warp scan + 1 atomic -------
__global__ __launch_bounds__(256) void assign_seg() {
    int i = blockIdx.x * 256 + threadIdx.x;
    int lane = threadIdx.x & 31;
    int c = (i < Nn) ? g_cnt[i] : 0;
    int s = c;
#pragma unroll
    for (int o = 1; o < 32; o <<= 1) {
        int n = __shfl_up_sync(0xFFFFFFFFu, s, o);
        if (lane >= o) s += n;
    }
    int base = 0;
    if (lane == 31) base = atomicAdd(&g_total, s);
    base = __shfl_sync(0xFFFFFFFFu, base, 31);
    int start = base + s - c;
    if (i < Nn) {
        g_start[i] = start;
        g_cursor[i] = start;
    }
}

// ---------------- scatter edges into grouped order ----------------
__global__ __launch_bounds__(256) void scatter(const int* __restrict__ src,
                                               const int* __restrict__ dst,
                                               const float* __restrict__ val) {
    int e = blockIdx.x * 256 + threadIdx.x;
    if (e >= NE) return;
    int d = dst[e];
    int p = atomicAdd(&g_cursor[d], 1);
    g_pedge[p] = make_int2(src[e], __float_as_int(val[e]));
}

// ---- GEMM1: xw = x @ W1 (50000x256 @ 256x64) ----
// BM=64, 128 threads, 8 rows x 4 cols per thread (proven R6 microtile),
// small blocks -> grid 782 -> ~5.3 blocks/SM, occupancy-limited no more.
#define G1_STR 66
__global__ __launch_bounds__(128) void gemm1(const float* __restrict__ x,
                                             const float* __restrict__ W1) {
    __shared__ __align__(16) float xs_t[32][G1_STR];  // [k][row], 8.25KB
    __shared__ __align__(16) float ws[32][64];        // 8KB
    int tid = threadIdx.x;
    int m0 = blockIdx.x * 64;
    int tx = tid & 15;        // col group: c0 = tx*4  (16*4 = 64 cols)
    int ty = tid >> 4;        // row group: r0 = ty*8  (8*8  = 64 rows)
    int c0 = tx * 4;
    int r0 = ty * 8;

    ull acc2[4][4];           // [row-pair][col]
#pragma unroll
    for (int j = 0; j < 4; j++)
#pragma unroll
        for (int c = 0; c < 4; c++) acc2[j][c] = 0ull;

    for (int k0 = 0; k0 < NF; k0 += 32) {
        // load x tile 64x32 -> transposed (4 float4 per thread)
#pragma unroll
        for (int p = 0; p < 4; p++) {
            int idx = tid + p * 128;       // 0..511 float4 slots
            int r   = idx >> 3;
            int kj  = (idx & 7) << 2;
            int row = m0 + r;
            float4 v = make_float4(0.f, 0.f, 0.f, 0.f);
            if (row < Nn)
                v = *reinterpret_cast<const float4*>(&x[(size_t)row * NF + k0 + kj]);
            xs_t[kj + 0][r] = v.x;
            xs_t[kj + 1][r] = v.y;
            xs_t[kj + 2][r] = v.z;
            xs_t[kj + 3][r] = v.w;
        }
        // load W tile 32x64 (4 float4 per thread)
#pragma unroll
        for (int p = 0; p < 4; p++) {
            int idx = tid + p * 128;       // 0..511
            int kk  = idx >> 4;
            int cc  = (idx & 15) << 2;
            float4 v = *reinterpret_cast<const float4*>(&W1[(size_t)(k0 + kk) * NH + cc]);
            *reinterpret_cast<float4*>(&ws[kk][cc]) = v;
        }
        __syncthreads();
#pragma unroll
        for (int k = 0; k < 32; k++) {
            float4 wv = *reinterpret_cast<const float4*>(&ws[k][c0]);
            ull w0, w1, w2, w3;
            PACK2(w0, wv.x, wv.x);
            PACK2(w1, wv.y, wv.y);
            PACK2(w2, wv.z, wv.z);
            PACK2(w3, wv.w, wv.w);
            const float* xr = &xs_t[k][r0];
            ull a0 = *reinterpret_cast<const ull*>(xr + 0);
            ull a1 = *reinterpret_cast<const ull*>(xr + 2);
            ull a2 = *reinterpret_cast<const ull*>(xr + 4);
            ull a3 = *reinterpret_cast<const ull*>(xr + 6);
            FMA2(acc2[0][0], a0, w0); FMA2(acc2[0][1], a0, w1);
            FMA2(acc2[0][2], a0, w2); FMA2(acc2[0][3], a0, w3);
            FMA2(acc2[1][0], a1, w0); FMA2(acc2[1][1], a1, w1);
            FMA2(acc2[1][2], a1, w2); FMA2(acc2[1][3], a1, w3);
            FMA2(acc2[2][0], a2, w0); FMA2(acc2[2][1], a2, w1);
            FMA2(acc2[2][2], a2, w2); FMA2(acc2[2][3], a2, w3);
            FMA2(acc2[3][0], a3, w0); FMA2(acc2[3][1], a3, w1);
            FMA2(acc2[3][2], a3, w2); FMA2(acc2[3][3], a3, w3);
        }
        __syncthreads();
    }
#pragma unroll
    for (int j = 0; j < 4; j++) {
        float e0[4], e1[4];
#pragma unroll
        for (int c = 0; c < 4; c++) UNPACK2(e0[c], e1[c], acc2[j][c]);
        int row = m0 + r0 + 2 * j;
        if (row < Nn)
            *reinterpret_cast<float4*>(&g_xw[(size_t)row * NH + c0]) =
                make_float4(e0[0], e0[1], e0[2], e0[3]);
        if (row + 1 < Nn)
            *reinterpret_cast<float4*>(&g_xw[(size_t)(row + 1) * NH + c0]) =
                make_float4(e1[0], e1[1], e1[2], e1[3]);
    }
}

// ---- SpMM1 gather + bias + relu: g_h[r] = relu(sum_e val*xw[src] + b1) ----
__global__ __launch_bounds__(256) void spmm1g(const float* __restrict__ b1) {
    int r = blockIdx.x * 8 + (threadIdx.x >> 5);
    if (r >= Nn) return;
    int lane = threadIdx.x & 31;
    float2 b = reinterpret_cast<const float2*>(b1)[lane];
    int e0 = g_start[r], e1 = e0 + g_cnt[r];
    float ax = 0.f, ay = 0.f, bx = 0.f, by = 0.f;
    int e = e0;
    for (; e + 2 <= e1; e += 2) {
        int2 ea = g_pedge[e];
        int2 eb = g_pedge[e + 1];
        float2 ta = reinterpret_cast<const float2*>(&g_xw[(size_t)ea.x * NH])[lane];
        float2 tb = reinterpret_cast<const float2*>(&g_xw[(size_t)eb.x * NH])[lane];
        float va = __int_as_float(ea.y);
        float vb = __int_as_float(eb.y);
        ax += va * ta.x; ay += va * ta.y;
        bx += vb * tb.x; by += vb * tb.y;
    }
    if (e < e1) {
        int2 ea = g_pedge[e];
        float2 ta = reinterpret_cast<const float2*>(&g_xw[(size_t)ea.x * NH])[lane];
        float va = __int_as_float(ea.y);
        ax += va * ta.x; ay += va * ta.y;
    }
    reinterpret_cast<float2*>(&g_h[(size_t)r * NH])[lane] =
        make_float2(fmaxf(ax + bx + b.x, 0.f), fmaxf(ay + by + b.y, 0.f));
}

// ---- SpMM2 gather: g_t[r] = sum_e val*g_h[src]  (64 feats) ----
__global__ __launch_bounds__(256) void spmm2k() {
    int r = blockIdx.x * 8 + (threadIdx.x >> 5);
    if (r >= Nn) return;
    int lane = threadIdx.x & 31;
    int e0 = g_start[r], e1 = e0 + g_cnt[r];
    float ax = 0.f, ay = 0.f, bx = 0.f, by = 0.f;
    int e = e0;
    for (; e + 2 <= e1; e += 2) {
        int2 ea = g_pedge[e];
        int2 eb = g_pedge[e + 1];
        float2 ta = reinterpret_cast<const float2*>(&g_h[(size_t)ea.x * NH])[lane];
        float2 tb = reinterpret_cast<const float2*>(&g_h[(size_t)eb.x * NH])[lane];
        float va = __int_as_float(ea.y);
        float vb = __int_as_float(eb.y);
        ax += va * ta.x; ay += va * ta.y;
        bx += vb * tb.x; by += vb * tb.y;
    }
    if (e < e1) {
        int2 ea = g_pedge[e];
        float2 ta = reinterpret_cast<const float2*>(&g_h[(size_t)ea.x * NH])[lane];
        float va = __int_as_float(ea.y);
        ax += va * ta.x; ay += va * ta.y;
    }
    reinterpret_cast<float2*>(&g_t[(size_t)r * NH])[lane] =
        make_float2(ax + bx, ay + by);
}

// ---- GEMM2 + finalize (R10 form) ----
#define G2_STR 68
__global__ __launch_bounds__(320) void gemm2fin(const float* __restrict__ eps,
                                                const float* __restrict__ W11,
                                                const float* __restrict__ b11,
                                                const float* __restrict__ W12,
                                                const float* __restrict__ b12,
                                                float* __restrict__ out) {
    __shared__ __align__(16) float hs_t[64][G2_STR];
    __shared__ __align__(16) float ws2[64][84];
    __shared__ float zs[64][80];
    __shared__ float bs[80];
    int tid = threadIdx.x;
    int r0b = blockIdx.x * 64;

    if (tid < 80) bs[tid] = (tid < NC) ? b11[tid] : b12[tid - NC];
    for (int idx = tid; idx < 64 * 80; idx += 320) {
        int k = idx / 80;
        int j = idx % 80;
        ws2[k][j] = (j < NC) ? W11[(size_t)k * NC + j] : W12[(size_t)k * NC + (j - NC)];
    }
    for (int idx = tid; idx < 1024; idx += 320) {
        int r  = idx >> 4;
        int kj = (idx & 15) << 2;
        int row = r0b + r;
        float4 v = make_float4(0.f, 0.f, 0.f, 0.f);
        if (row < Nn)
            v = *reinterpret_cast<const float4*>(&g_t[(size_t)row * NH + kj]);
        hs_t[kj + 0][r] = v.x;
        hs_t[kj + 1][r] = v.y;
        hs_t[kj + 2][r] = v.z;
        hs_t[kj + 3][r] = v.w;
    }
    __syncthreads();

    int tx = tid % 20;
    int ty = tid / 20;
    int c0 = tx * 4;
    int r0 = ty * 4;

    ull acc2[2][4];
#pragma unroll
    for (int j = 0; j < 2; j++)
#pragma unroll
        for (int c = 0; c < 4; c++) acc2[j][c] = 0ull;

#pragma unroll
    for (int k = 0; k < 64; k++) {
        float4 wq = *reinterpret_cast<const float4*>(&ws2[k][c0]);
        ull w0, w1, w2, w3;
        PACK2(w0, wq.x, wq.x);
        PACK2(w1, wq.y, wq.y);
        PACK2(w2, wq.z, wq.z);
        PACK2(w3, wq.w, wq.w);
        const float* hr = &hs_t[k][r0];
        ull a0 = *reinterpret_cast<const ull*>(hr + 0);
        ull a1 = *reinterpret_cast<const ull*>(hr + 2);
        FMA2(acc2[0][0], a0, w0); FMA2(acc2[0][1], a0, w1);
        FMA2(acc2[0][2], a0, w2); FMA2(acc2[0][3], a0, w3);
        FMA2(acc2[1][0], a1, w0); FMA2(acc2[1][1], a1, w1);
        FMA2(acc2[1][2], a1, w2); FMA2(acc2[1][3], a1, w3);
    }
#pragma unroll
    for (int j = 0; j < 2; j++) {
#pragma unroll
        for (int c = 0; c < 4; c++) {
            float lo, hi;
            UNPACK2(lo, hi, acc2[j][c]);
            zs[r0 + 2 * j][c0 + c]     = lo;
            zs[r0 + 2 * j + 1][c0 + c] = hi;
        }
    }
    __syncthreads();

    int w = tid >> 5;
    int lane = tid & 31;
    for (int r = w; r < 64; r += 10) {
        int row = r0b + r;
        if (row >= Nn) continue;
        const float* zr = zs[r];
        float z0 = eps[(size_t)row * NC + lane] * expf(zr[NC + lane] + bs[NC + lane])
                 + zr[lane] + bs[lane];
        float z1 = -CUDART_INF_F;
        if (lane < 8) {
            int jj = 32 + lane;
            z1 = eps[(size_t)row * NC + jj] * expf(zr[NC + jj] + bs[NC + jj])
               + zr[jj] + bs[jj];
        }
        float mx = fmaxf(z0, z1);
#pragma unroll
        for (int o = 16; o > 0; o >>= 1)
            mx = fmaxf(mx, __shfl_xor_sync(0xFFFFFFFFu, mx, o));
        float sm = expf(z0 - mx) + ((lane < 8) ? expf(z1 - mx) : 0.f);
#pragma unroll
        for (int o = 16; o > 0; o >>= 1)
            sm += __shfl_xor_sync(0xFFFFFFFFu, sm, o);
        float lse = logf(sm) + mx;
        out[(size_t)row * NC + lane] = z0 - lse;
        if (lane < 8)
            out[(size_t)row * NC + 32 + lane] = z1 - lse;
    }
}

extern "C" void kernel_launch(void* const* d_in, const int* in_sizes, int n_in,
                              void* d_out, int out_size) {
    const float* x    = (const float*)d_in[0];
    const int*   esrc = (const int*)d_in[1];
    const int*   edst = (const int*)d_in[2];
    const float* evl  = (const float*)d_in[3];
    const float* eps  = (const float*)d_in[4];
    const float* W1   = (const float*)d_in[5];
    const float* b1   = (const float*)d_in[6];
    const float* W11  = (const float*)d_in[7];
    const float* b11  = (const float*)d_in[8];
    const float* W12  = (const float*)d_in[9];
    const float* b12  = (const float*)d_in[10];
    float* out = (float*)d_out;

    // side stream + events, created once (first call is the non-captured
    // correctness run, so creation never happens during graph capture)
    static cudaStream_t s2 = nullptr;
    static cudaEvent_t evA = nullptr, evB = nullptr;
    if (s2 == nullptr) {
        cudaStreamCreateWithFlags(&s2, cudaStreamNonBlocking);
        cudaEventCreateWithFlags(&evA, cudaEventDisableTiming);
        cudaEventCreateWithFlags(&evB, cudaEventDisableTiming);
    }

    // fork: gemm1 (independent of CSR build) runs on s2
    cudaEventRecord(evA, 0);
    cudaStreamWaitEvent(s2, evA, 0);

    zero_cnt<<<(Nn + 255) / 256, 256>>>();
    hist<<<(NE + 255) / 256, 256>>>(edst);
    assign_seg<<<(Nn + 255) / 256, 256>>>();
    gemm1<<<(Nn + 63) / 64, 128, 0, s2>>>(x, W1);   // 4th submission -> ncu snapshot
    scatter<<<(NE + 255) / 256, 256>>>(esrc, edst, evl);

    // join: spmm1g needs both scatter (stream 0) and gemm1 (s2)
    cudaEventRecord(evB, s2);
    cudaStreamWaitEvent(0, evB, 0);

    spmm1g<<<(Nn + 7) / 8, 256>>>(b1);
    spmm2k<<<(Nn + 7) / 8, 256>>>();
    gemm2fin<<<(Nn + 63) / 64, 320>>>(eps, W11, b11, W12, b12, out);
}

// round 14
// speedup vs baseline: 1.2068x; 1.0478x over previous
#include <cuda_runtime.h>
#include <cuda_fp16.h>
#include <math_constants.h>

#define Nn 50000
#define NF 256
#define NH 64
#define NC 40
#define NE 800000

typedef unsigned long long ull;

// packed f32x2 helpers (FFMA2 path — ptxas won't emit from plain C++)
#define FMA2(acc, a, b) asm("fma.rn.f32x2 %0, %1, %2, %0;" : "+l"(acc) : "l"(a), "l"(b))
#define PACK2(d, lo, hi) asm("mov.b64 %0, {%1, %2};" : "=l"(d) : "f"(lo), "f"(hi))
#define UNPACK2(lo, hi, s) asm("mov.b64 {%0, %1}, %2;" : "=f"(lo), "=f"(hi) : "l"(s))

// -------- device scratch (no allocs allowed) --------
__device__ __half g_xw[(size_t)Nn * NH];   // x @ W1   (fp16 staging)
__device__ __half g_h[(size_t)Nn * NH];    // relu(A·xw + b1)  (fp16 staging)
__device__ float  g_t[(size_t)Nn * NH];    // A·g_h  (fp32)
__device__ int    g_cnt[Nn];               // per-dst edge counts
__device__ int    g_start[Nn];             // per-dst segment start
__device__ int    g_cursor[Nn];            // scatter cursors
__device__ int    g_total;                 // global segment allocator
__device__ int2   g_pedge[NE];             // permuted (src, val-bits) grouped by dst

// ---------------- zero counts + allocator ----------------
__global__ __launch_bounds__(256) void zero_cnt() {
    int i = blockIdx.x * 256 + threadIdx.x;
    if (i < Nn) g_cnt[i] = 0;
    if (i == 0) g_total = 0;
}

// ---------------- histogram of dst ----------------
__global__ __launch_bounds__(256) void hist(const int* __restrict__ dst) {
    int e = blockIdx.x * 256 + threadIdx.x;
    if (e < NE) atomicAdd(&g_cnt[dst[e]], 1);
}

// ------- segment assign: disjoint per-row ranges via warp scan + 1 atomic -------
__global__ __launch_bounds__(256) void assign_seg() {
    int i = blockIdx.x * 256 + threadIdx.x;
    int lane = threadIdx.x & 31;
    int c = (i < Nn) ? g_cnt[i] : 0;
    int s = c;
#pragma unroll
    for (int o = 1; o < 32; o <<= 1) {
        int n = __shfl_up_sync(0xFFFFFFFFu, s, o);
        if (lane >= o) s += n;
    }
    int base = 0;
    if (lane == 31) base = atomicAdd(&g_total, s);
    base = __shfl_sync(0xFFFFFFFFu, base, 31);
    int start = base + s - c;
    if (i < Nn) {
        g_start[i] = start;
        g_cursor[i] = start;
    }
}

// ---------------- scatter edges into grouped order ----------------
__global__ __launch_bounds__(256) void scatter(const int* __restrict__ src,
                                               const int* __restrict__ dst,
                                               const float* __restrict__ val) {
    int e = blockIdx.x * 256 + threadIdx.x;
    if (e >= NE) return;
    int d = dst[e];
    int p = atomicAdd(&g_cursor[d], 1);
    g_pedge[p] = make_int2(src[e], __float_as_int(val[e]));
}

// ---- GEMM1: xw = x @ W1 (50000x256 @ 256x64), fp16 output ----
#define G1_STR 66
__global__ __launch_bounds__(128) void gemm1(const float* __restrict__ x,
                                             const float* __restrict__ W1) {
    __shared__ __align__(16) float xs_t[32][G1_STR];  // [k][row], 8.25KB
    __shared__ __align__(16) float ws[32][64];        // 8KB
    int tid = threadIdx.x;
    int m0 = blockIdx.x * 64;
    int tx = tid & 15;        // col group: c0 = tx*4
    int ty = tid >> 4;        // row group: r0 = ty*8
    int c0 = tx * 4;
    int r0 = ty * 8;

    ull acc2[4][4];
#pragma unroll
    for (int j = 0; j < 4; j++)
#pragma unroll
        for (int c = 0; c < 4; c++) acc2[j][c] = 0ull;

    for (int k0 = 0; k0 < NF; k0 += 32) {
#pragma unroll
        for (int p = 0; p < 4; p++) {
            int idx = tid + p * 128;
            int r   = idx >> 3;
            int kj  = (idx & 7) << 2;
            int row = m0 + r;
            float4 v = make_float4(0.f, 0.f, 0.f, 0.f);
            if (row < Nn)
                v = *reinterpret_cast<const float4*>(&x[(size_t)row * NF + k0 + kj]);
            xs_t[kj + 0][r] = v.x;
            xs_t[kj + 1][r] = v.y;
            xs_t[kj + 2][r] = v.z;
            xs_t[kj + 3][r] = v.w;
        }
#pragma unroll
        for (int p = 0; p < 4; p++) {
            int idx = tid + p * 128;
            int kk  = idx >> 4;
            int cc  = (idx & 15) << 2;
            float4 v = *reinterpret_cast<const float4*>(&W1[(size_t)(k0 + kk) * NH + cc]);
            *reinterpret_cast<float4*>(&ws[kk][cc]) = v;
        }
        __syncthreads();
#pragma unroll
        for (int k = 0; k < 32; k++) {
            float4 wv = *reinterpret_cast<const float4*>(&ws[k][c0]);
            ull w0, w1, w2, w3;
            PACK2(w0, wv.x, wv.x);
            PACK2(w1, wv.y, wv.y);
            PACK2(w2, wv.z, wv.z);
            PACK2(w3, wv.w, wv.w);
            const float* xr = &xs_t[k][r0];
            ull a0 = *reinterpret_cast<const ull*>(xr + 0);
            ull a1 = *reinterpret_cast<const ull*>(xr + 2);
            ull a2 = *reinterpret_cast<const ull*>(xr + 4);
            ull a3 = *reinterpret_cast<const ull*>(xr + 6);
            FMA2(acc2[0][0], a0, w0); FMA2(acc2[0][1], a0, w1);
            FMA2(acc2[0][2], a0, w2); FMA2(acc2[0][3], a0, w3);
            FMA2(acc2[1][0], a1, w0); FMA2(acc2[1][1], a1, w1);
            FMA2(acc2[1][2], a1, w2); FMA2(acc2[1][3], a1, w3);
            FMA2(acc2[2][0], a2, w0); FMA2(acc2[2][1], a2, w1);
            FMA2(acc2[2][2], a2, w2); FMA2(acc2[2][3], a2, w3);
            FMA2(acc2[3][0], a3, w0); FMA2(acc2[3][1], a3, w1);
            FMA2(acc2[3][2], a3, w2); FMA2(acc2[3][3], a3, w3);
        }
        __syncthreads();
    }
#pragma unroll
    for (int j = 0; j < 4; j++) {
        float e0[4], e1[4];
#pragma unroll
        for (int c = 0; c < 4; c++) UNPACK2(e0[c], e1[c], acc2[j][c]);
        int row = m0 + r0 + 2 * j;
        if (row < Nn) {
            __half2 h0 = __floats2half2_rn(e0[0], e0[1]);
            __half2 h1 = __floats2half2_rn(e0[2], e0[3]);
            *reinterpret_cast<__half2*>(&g_xw[(size_t)row * NH + c0]) = h0;
            *reinterpret_cast<__half2*>(&g_xw[(size_t)row * NH + c0 + 2]) = h1;
        }
        if (row + 1 < Nn) {
            __half2 h0 = __floats2half2_rn(e1[0], e1[1]);
            __half2 h1 = __floats2half2_rn(e1[2], e1[3]);
            *reinterpret_cast<__half2*>(&g_xw[(size_t)(row + 1) * NH + c0]) = h0;
            *reinterpret_cast<__half2*>(&g_xw[(size_t)(row + 1) * NH + c0 + 2]) = h1;
        }
    }
}

// ---- SpMM1 gather (fp16 rows) + bias + relu -> fp16 g_h ----
__global__ __launch_bounds__(256) void spmm1g(const float* __restrict__ b1) {
    int r = blockIdx.x * 8 + (threadIdx.x >> 5);
    if (r >= Nn) return;
    int lane = threadIdx.x & 31;
    float2 b = reinterpret_cast<const float2*>(b1)[lane];
    int e0 = g_start[r], e1 = e0 + g_cnt[r];
    float ax = 0.f, ay = 0.f, bx = 0.f, by = 0.f;
    int e = e0;
    for (; e + 2 <= e1; e += 2) {
        int2 ea = g_pedge[e];
        int2 eb = g_pedge[e + 1];
        __half2 ha = reinterpret_cast<const __half2*>(&g_xw[(size_t)ea.x * NH])[lane];
        __half2 hb = reinterpret_cast<const __half2*>(&g_xw[(size_t)eb.x * NH])[lane];
        float2 ta = __half22float2(ha);
        float2 tb = __half22float2(hb);
        float va = __int_as_float(ea.y);
        float vb = __int_as_float(eb.y);
        ax += va * ta.x; ay += va * ta.y;
        bx += vb * tb.x; by += vb * tb.y;
    }
    if (e < e1) {
        int2 ea = g_pedge[e];
        __half2 ha = reinterpret_cast<const __half2*>(&g_xw[(size_t)ea.x * NH])[lane];
        float2 ta = __half22float2(ha);
        float va = __int_as_float(ea.y);
        ax += va * ta.x; ay += va * ta.y;
    }
    float rx = fmaxf(ax + bx + b.x, 0.f);
    float ry = fmaxf(ay + by + b.y, 0.f);
    reinterpret_cast<__half2*>(&g_h[(size_t)r * NH])[lane] = __floats2half2_rn(rx, ry);
}

// ---- SpMM2 gather (fp16 rows): g_t[r] = sum_e val*g_h[src] (fp32 out) ----
__global__ __launch_bounds__(256) void spmm2k() {
    int r = blockIdx.x * 8 + (threadIdx.x >> 5);
    if (r >= Nn) return;
    int lane = threadIdx.x & 31;
    int e0 = g_start[r], e1 = e0 + g_cnt[r];
    float ax = 0.f, ay = 0.f, bx = 0.f, by = 0.f;
    int e = e0;
    for (; e + 2 <= e1; e += 2) {
        int2 ea = g_pedge[e];
        int2 eb = g_pedge[e + 1];
        __half2 ha = reinterpret_cast<const __half2*>(&g_h[(size_t)ea.x * NH])[lane];
        __half2 hb = reinterpret_cast<const __half2*>(&g_h[(size_t)eb.x * NH])[lane];
        float2 ta = __half22float2(ha);
        float2 tb = __half22float2(hb);
        float va = __int_as_float(ea.y);
        float vb = __int_as_float(eb.y);
        ax += va * ta.x; ay += va * ta.y;
        bx += vb * tb.x; by += vb * tb.y;
    }
    if (e < e1) {
        int2 ea = g_pedge[e];
        __half2 ha = reinterpret_cast<const __half2*>(&g_h[(size_t)ea.x * NH])[lane];
        float2 ta = __half22float2(ha);
        float va = __int_as_float(ea.y);
        ax += va * ta.x; ay += va * ta.y;
    }
    reinterpret_cast<float2*>(&g_t[(size_t)r * NH])[lane] =
        make_float2(ax + bx, ay + by);
}

// ---- GEMM2 + finalize (R10 form) ----
#define G2_STR 68
__global__ __launch_bounds__(320) void gemm2fin(const float* __restrict__ eps,
                                                const float* __restrict__ W11,
                                                const float* __restrict__ b11,
                                                const float* __restrict__ W12,
                                                const float* __restrict__ b12,
                                                float* __restrict__ out) {
    __shared__ __align__(16) float hs_t[64][G2_STR];
    __shared__ __align__(16) float ws2[64][84];
    __shared__ float zs[64][80];
    __shared__ float bs[80];
    int tid = threadIdx.x;
    int r0b = blockIdx.x * 64;

    if (tid < 80) bs[tid] = (tid < NC) ? b11[tid] : b12[tid - NC];
    for (int idx = tid; idx < 64 * 80; idx += 320) {
        int k = idx / 80;
        int j = idx % 80;
        ws2[k][j] = (j < NC) ? W11[(size_t)k * NC + j] : W12[(size_t)k * NC + (j - NC)];
    }
    for (int idx = tid; idx < 1024; idx += 320) {
        int r  = idx >> 4;
        int kj = (idx & 15) << 2;
        int row = r0b + r;
        float4 v = make_float4(0.f, 0.f, 0.f, 0.f);
        if (row < Nn)
            v = *reinterpret_cast<const float4*>(&g_t[(size_t)row * NH + kj]);
        hs_t[kj + 0][r] = v.x;
        hs_t[kj + 1][r] = v.y;
        hs_t[kj + 2][r] = v.z;
        hs_t[kj + 3][r] = v.w;
    }
    __syncthreads();

    int tx = tid % 20;
    int ty = tid / 20;
    int c0 = tx * 4;
    int r0 = ty * 4;

    ull acc2[2][4];
#pragma unroll
    for (int j = 0; j < 2; j++)
#pragma unroll
        for (int c = 0; c < 4; c++) acc2[j][c] = 0ull;

#pragma unroll
    for (int k = 0; k < 64; k++) {
        float4 wq = *reinterpret_cast<const float4*>(&ws2[k][c0]);
        ull w0, w1, w2, w3;
        PACK2(w0, wq.x, wq.x);
        PACK2(w1, wq.y, wq.y);
        PACK2(w2, wq.z, wq.z);
        PACK2(w3, wq.w, wq.w);
        const float* hr = &hs_t[k][r0];
        ull a0 = *reinterpret_cast<const ull*>(hr + 0);
        ull a1 = *reinterpret_cast<const ull*>(hr + 2);
        FMA2(acc2[0][0], a0, w0); FMA2(acc2[0][1], a0, w1);
        FMA2(acc2[0][2], a0, w2); FMA2(acc2[0][3], a0, w3);
        FMA2(acc2[1][0], a1, w0); FMA2(acc2[1][1], a1, w1);
        FMA2(acc2[1][2], a1, w2); FMA2(acc2[1][3], a1, w3);
    }
#pragma unroll
    for (int j = 0; j < 2; j++) {
#pragma unroll
        for (int c = 0; c < 4; c++) {
            float lo, hi;
            UNPACK2(lo, hi, acc2[j][c]);
            zs[r0 + 2 * j][c0 + c]     = lo;
            zs[r0 + 2 * j + 1][c0 + c] = hi;
        }
    }
    __syncthreads();

    int w = tid >> 5;
    int lane = tid & 31;
    for (int r = w; r < 64; r += 10) {
        int row = r0b + r;
        if (row >= Nn) continue;
        const float* zr = zs[r];
        float z0 = eps[(size_t)row * NC + lane] * expf(zr[NC + lane] + bs[NC + lane])
                 + zr[lane] + bs[lane];
        float z1 = -CUDART_INF_F;
        if (lane < 8) {
            int jj = 32 + lane;
            z1 = eps[(size_t)row * NC + jj] * expf(zr[NC + jj] + bs[NC + jj])
               + zr[jj] + bs[jj];
        }
        float mx = fmaxf(z0, z1);
#pragma unroll
        for (int o = 16; o > 0; o >>= 1)
            mx = fmaxf(mx, __shfl_xor_sync(0xFFFFFFFFu, mx, o));
        float sm = expf(z0 - mx) + ((lane < 8) ? expf(z1 - mx) : 0.f);
#pragma unroll
        for (int o = 16; o > 0; o >>= 1)
            sm += __shfl_xor_sync(0xFFFFFFFFu, sm, o);
        float lse = logf(sm) + mx;
        out[(size_t)row * NC + lane] = z0 - lse;
        if (lane < 8)
            out[(size_t)row * NC + 32 + lane] = z1 - lse;
    }
}

extern "C" void kernel_launch(void* const* d_in, const int* in_sizes, int n_in,
                              void* d_out, int out_size) {
    const float* x    = (const float*)d_in[0];
    const int*   esrc = (const int*)d_in[1];
    const int*   edst = (const int*)d_in[2];
    const float* evl  = (const float*)d_in[3];
    const float* eps  = (const float*)d_in[4];
    const float* W1   = (const float*)d_in[5];
    const float* b1   = (const float*)d_in[6];
    const float* W11  = (const float*)d_in[7];
    const float* b11  = (const float*)d_in[8];
    const float* W12  = (const float*)d_in[9];
    const float* b12  = (const float*)d_in[10];
    float* out = (float*)d_out;

    static cudaStream_t s2 = nullptr;
    static cudaEvent_t evA = nullptr, evB = nullptr;
    if (s2 == nullptr) {
        cudaStreamCreateWithFlags(&s2, cudaStreamNonBlocking);
        cudaEventCreateWithFlags(&evA, cudaEventDisableTiming);
        cudaEventCreateWithFlags(&evB, cudaEventDisableTiming);
    }

    // fork: gemm1 (independent of CSR build) runs on s2
    cudaEventRecord(evA, 0);
    cudaStreamWaitEvent(s2, evA, 0);

    zero_cnt<<<(Nn + 255) / 256, 256>>>();
    hist<<<(NE + 255) / 256, 256>>>(edst);
    assign_seg<<<(Nn + 255) / 256, 256>>>();
    gemm1<<<(Nn + 63) / 64, 128, 0, s2>>>(x, W1);   // 4th submission -> ncu snapshot
    scatter<<<(NE + 255) / 256, 256>>>(esrc, edst, evl);

    // join: spmm1g needs both scatter (stream 0) and gemm1 (s2)
    cudaEventRecord(evB, s2);
    cudaStreamWaitEvent(0, evB, 0);

    spmm1g<<<(Nn + 7) / 8, 256>>>(b1);
    spmm2k<<<(Nn + 7) / 8, 256>>>();
    gemm2fin<<<(Nn + 63) / 64, 320>>>(eps, W11, b11, W12, b12, out);
}